// round 10
// baseline (speedup 1.0000x reference)
#include <cuda_runtime.h>
#include <cstdint>

// Row-wise top-k threshold mask.
// out[i,j] = x[i,j] if x[i,j] >= (k-th largest of row i) else 0.
// One 256-thread CTA per row, 8 CTAs/SM.
// Zero-fill of out is offloaded to TMA bulk stores (smem zero buffer ->
// global), so SM warps only run the load+compact stream. Candidates
// (v >= T0, count-validated) resolved by exact radix select; survivors
// scattered after the bulk stores complete. x is never re-read on the
// fast path. Full-row fallback keeps arbitrary inputs correct.

constexpr int COLS    = 16384;
constexpr int THREADS = 256;
constexpr int VEC4    = COLS / THREADS / 4;   // 16 float4 per thread
constexpr int CAP     = 2048;                 // candidate buffer capacity
constexpr int ZBYTES  = 8192;                 // smem zero buffer (8KB)
constexpr int ROWB    = COLS * 4;             // 64KB per row
constexpr int NBULK   = ROWB / ZBYTES;        // 8 bulk stores per row

__device__ __forceinline__ unsigned f2key(float f) {
    unsigned u = __float_as_uint(f);
    unsigned m = (unsigned)((int)u >> 31) | 0x80000000u;
    return u ^ m;
}
__device__ __forceinline__ float key2f(unsigned k) {
    unsigned u = (k & 0x80000000u) ? (k & 0x7FFFFFFFu) : ~k;
    return __uint_as_float(u);
}

// Block radix-select step over 256 bins (256 threads, one bin each).
__device__ __forceinline__ unsigned select_digit(
    int* s_hist, int* s_warp, int* s_kk, unsigned* s_digit, int tid, int lane)
{
    int h = s_hist[255 - tid];
    int v = h;
    #pragma unroll
    for (int o = 1; o < 32; o <<= 1) {
        int n = __shfl_up_sync(0xFFFFFFFFu, v, o);
        if (lane >= o) v += n;
    }
    if (lane == 31) s_warp[tid >> 5] = v;
    __syncthreads();
    if (tid < 8) {
        int ws = s_warp[tid];
        #pragma unroll
        for (int o = 1; o < 8; o <<= 1) {
            int n = __shfl_up_sync(0xFFu, ws, o);
            if (tid >= o) ws += n;
        }
        s_warp[tid] = ws;
    }
    const int kk_cur = *s_kk;
    __syncthreads();
    const int incl   = v + ((tid >= 32) ? s_warp[(tid >> 5) - 1] : 0);
    const int cnt_gt = incl - h;
    if (cnt_gt < kk_cur && kk_cur <= incl) {
        *s_digit = (unsigned)(255 - tid);
        *s_kk    = kk_cur - cnt_gt;
    }
    __syncthreads();
    return *s_digit;
}

__global__ __launch_bounds__(THREADS, 8)
void topk_mask_kernel(const float* __restrict__ x,
                      float* __restrict__ out,
                      const int* __restrict__ kptr)
{
    __shared__ int                s_hist[256];
    __shared__ int                s_warp[8];
    __shared__ unsigned long long s_cand[CAP];          // (key << 32) | col
    __shared__ int                s_ncand;
    __shared__ int                s_kk;
    __shared__ unsigned           s_digit;
    __shared__ __align__(16) float4 s_zero[ZBYTES / 16]; // 8KB of zeros

    const int    tid  = threadIdx.x;
    const int    lane = tid & 31;
    const size_t base = (size_t)blockIdx.x * COLS;
    const float4* xv  = reinterpret_cast<const float4*>(x + base);

    const int kk0 = (kptr != nullptr) ? kptr[0] : 64;
    if (tid == 0) { s_ncand = 0; s_kk = kk0; }

    // Zero the smem staging buffer (generic proxy), then fence for async proxy.
    const float4 z4 = make_float4(0.f, 0.f, 0.f, 0.f);
    #pragma unroll
    for (int i = 0; i < ZBYTES / 16 / THREADS; i++)
        s_zero[tid + i * THREADS] = z4;
    asm volatile("fence.proxy.async.shared::cta;" ::: "memory");
    __syncthreads();

    // ---- Kick off TMA bulk zero-fill of this row's output (async) ----
    if (tid == 0) {
        uint32_t zaddr;
        asm("{ .reg .u64 t; cvta.to.shared.u64 t, %1; cvt.u32.u64 %0, t; }"
            : "=r"(zaddr) : "l"(s_zero));
        #pragma unroll
        for (int b = 0; b < NBULK; b++) {
            asm volatile(
                "cp.async.bulk.global.shared::cta.bulk_group [%0], [%1], %2;"
                :: "l"(reinterpret_cast<char*>(out + base) + b * ZBYTES),
                   "r"(zaddr), "n"(ZBYTES)
                : "memory");
        }
        asm volatile("cp.async.bulk.commit_group;" ::: "memory");
    }

    // ---- Pass A: pure load + compact stream (no stores from warps) ----
    const float T0 = 2.0f;
    #pragma unroll
    for (int j = 0; j < VEC4; j++) {
        const int pos = tid + j * THREADS;
        float4 v = xv[pos];
        float vs[4] = {v.x, v.y, v.z, v.w};
        #pragma unroll
        for (int t = 0; t < 4; t++) {
            if (vs[t] >= T0) {
                const int idx = atomicAdd(&s_ncand, 1);
                if (idx < CAP)
                    s_cand[idx] = ((unsigned long long)f2key(vs[t]) << 32)
                                | (unsigned)(pos * 4 + t);
            }
        }
    }
    __syncthreads();
    const int  ncand  = s_ncand;
    const bool useBuf = (ncand >= kk0 && ncand <= CAP);

    // ---- Resolve all 32 bits: 4 byte-radix passes over candidates ----
    unsigned prefix = 0, prefmask = 0;
    #pragma unroll 1
    for (int p = 0; p < 4; p++) {
        const int shift = 24 - p * 8;

        s_hist[tid] = 0;
        __syncthreads();

        if (useBuf) {
            const int nloop = (ncand + THREADS - 1) / THREADS * THREADS;
            for (int i = tid; i < nloop; i += THREADS) {
                const unsigned key  = (i < ncand) ? (unsigned)(s_cand[i] >> 32) : 0u;
                const bool     cand = (i < ncand) && ((key & prefmask) == prefix);
                const unsigned d    = cand ? ((key >> shift) & 255u) : 0xFFFFFFFFu;
                const unsigned m    = __match_any_sync(0xFFFFFFFFu, d);
                if (cand && lane == (__ffs(m) - 1)) atomicAdd(&s_hist[d], __popc(m));
            }
        } else {
            // fallback: full-row scan from gmem (non-normal inputs only)
            #pragma unroll 4
            for (int j = 0; j < VEC4; j++) {
                float4 v = xv[tid + j * THREADS];
                unsigned ks[4] = {f2key(v.x), f2key(v.y), f2key(v.z), f2key(v.w)};
                #pragma unroll
                for (int t = 0; t < 4; t++) {
                    const bool     cand = ((ks[t] & prefmask) == prefix);
                    const unsigned d    = cand ? ((ks[t] >> shift) & 255u) : 0xFFFFFFFFu;
                    const unsigned m    = __match_any_sync(0xFFFFFFFFu, d);
                    if (cand && lane == (__ffs(m) - 1)) atomicAdd(&s_hist[d], __popc(m));
                }
            }
        }
        __syncthreads();

        const unsigned dig = select_digit(s_hist, s_warp, &s_kk, &s_digit, tid, lane);
        prefix   |= dig << shift;
        prefmask |= 255u << shift;
        __syncthreads();
    }

    const unsigned thresh = prefix;          // exact key of the k-th largest

    // ---- Wait for the bulk zero-fill before overwriting survivors ----
    if (tid == 0)
        asm volatile("cp.async.bulk.wait_group 0;" ::: "memory");
    __syncthreads();

    // ---- Pass B: scatter survivors only (~k per row) ----
    if (useBuf) {
        for (int i = tid; i < ncand; i += THREADS) {
            const unsigned long long kv = s_cand[i];
            const unsigned key = (unsigned)(kv >> 32);
            if (key >= thresh)
                out[base + (unsigned)(kv & 0xFFFFFFFFu)] = key2f(key);
        }
    } else {
        // fallback: conditional re-read scatter (out already zeroed)
        const float t = key2f(thresh);
        #pragma unroll 4
        for (int j = 0; j < VEC4; j++) {
            const int pos = tid + j * THREADS;
            float4 v = xv[pos];
            float vs[4] = {v.x, v.y, v.z, v.w};
            #pragma unroll
            for (int q = 0; q < 4; q++)
                if (vs[q] >= t) out[base + pos * 4 + q] = vs[q];
        }
    }
}

extern "C" void kernel_launch(void* const* d_in, const int* in_sizes, int n_in,
                              void* d_out, int out_size)
{
    const float* x  = (const float*)d_in[0];
    const int*   kp = (n_in >= 2) ? (const int*)d_in[1] : nullptr;
    float*       o  = (float*)d_out;

    const int rows = in_sizes[0] / COLS;
    topk_mask_kernel<<<rows, THREADS>>>(x, o, kp);
}